// round 6
// baseline (speedup 1.0000x reference)
#include <cuda_runtime.h>
#include <stdint.h>

#define NN 50000
#define NE 800000
#define D  96
#define NC 16
#define ST (NN*D)        // 4,800,000

// ---------------- scratch (static device globals; no allocation) ----------
__device__ __align__(16) float g_X[ST];   // dropout+scaled input to message pass
__device__ __align__(16) float g_Y[ST];   // aggregation buffer
__device__ __align__(16) float g_H[ST];   // layer output
__device__ int   g_cO[NN];
__device__ int   g_cI[NN];
__device__ float g_iO[NN];
__device__ float g_iI[NN];

// ---------------- threefry2x32-20 (matches JAX) ----------------------------
__device__ __host__ __forceinline__ void tf2x32(uint32_t k0, uint32_t k1,
                                                uint32_t& x0, uint32_t& x1) {
    uint32_t k2 = k0 ^ k1 ^ 0x1BD11BDAu;
    x0 += k0; x1 += k1;
#define TF_R(r) { x0 += x1; x1 = (x1 << (r)) | (x1 >> (32 - (r))); x1 ^= x0; }
    TF_R(13) TF_R(15) TF_R(26) TF_R(6)   x0 += k1; x1 += k2 + 1u;
    TF_R(17) TF_R(29) TF_R(16) TF_R(24)  x0 += k2; x1 += k0 + 2u;
    TF_R(13) TF_R(15) TF_R(26) TF_R(6)   x0 += k0; x1 += k1 + 3u;
    TF_R(17) TF_R(29) TF_R(16) TF_R(24)  x0 += k1; x1 += k2 + 4u;
    TF_R(13) TF_R(15) TF_R(26) TF_R(6)   x0 += k2; x1 += k0 + 5u;
#undef TF_R
}

// ---------------- degree kernels -------------------------------------------
__global__ void k_zero() {
    int i = blockIdx.x * blockDim.x + threadIdx.x;
    if (i < NN) { g_cO[i] = 0; g_cI[i] = 0; }
}

__global__ void k_count(const int* __restrict__ src, const int* __restrict__ dst) {
    int e = blockIdx.x * blockDim.x + threadIdx.x;
    if (e < NE) {
        atomicAdd(&g_cO[src[e]], 1);
        atomicAdd(&g_cI[dst[e]], 1);
    }
}

__global__ void k_fin() {
    int i = blockIdx.x * blockDim.x + threadIdx.x;
    if (i < NN) {
        g_iO[i] = (float)(1.0 / sqrt((double)max(g_cO[i], 1)));
        g_iI[i] = (float)(1.0 / sqrt((double)max(g_cI[i], 1)));
    }
}

// ---------------- dropout + D_out^-1/2 scale, zero agg ---------------------
// JAX partitionable threefry (_threefry_random_bits_partitionable):
//   counts1, counts2 = hi/lo 32-bit words of 64-bit iota  -> (0, i) here
//   bits1, bits2 = threefry2x32(key, (counts1, counts2))
//   bits[i] = bits1 ^ bits2                                (bit_width == 32)
// keep ⇔ uniform(bits) < 0.5 ⇔ msb(bits) == 0.
__global__ void k_prep(const float* __restrict__ hin, uint32_t k0, uint32_t k1) {
    int t = blockIdx.x * blockDim.x + threadIdx.x;
    if (t >= ST / 4) return;
    int j = t * 4;
    float4 a = *(const float4*)(hin + j);
    float s = g_iO[j / D] * 2.0f;             // *2 = /(1-p)
    float v[4] = {a.x, a.y, a.z, a.w};
#pragma unroll
    for (int i = 0; i < 4; i++) {
        uint32_t x0 = 0u, x1 = (uint32_t)(j + i);
        tf2x32(k0, k1, x0, x1);
        uint32_t bits = x0 ^ x1;
        v[i] = (bits < 0x80000000u) ? v[i] * s : 0.0f;
    }
    *(float4*)(g_X + j) = make_float4(v[0], v[1], v[2], v[3]);
    *(float4*)(g_Y + j) = make_float4(0.f, 0.f, 0.f, 0.f);
}

// ---------------- edge gather + scatter-add (v4 reds) ----------------------
// 8 lanes per edge; each lane handles 3 float4 chunks (24 total = 96 floats).
__global__ void k_edge(const float* __restrict__ ew,
                       const int* __restrict__ src, const int* __restrict__ dst) {
    int tid = blockIdx.x * blockDim.x + threadIdx.x;
    int e = tid >> 3;
    if (e >= NE) return;
    int sub = tid & 7;
    int s = src[e], d = dst[e];
    float w = ew[e];
    const float4* xs = (const float4*)(g_X + s * D);
    float4* yd = (float4*)(g_Y + d * D);
#pragma unroll
    for (int i = 0; i < 3; i++) {
        int c = sub + i * 8;
        float4 v = xs[c];
        v.x *= w; v.y *= w; v.z *= w; v.w *= w;
        asm volatile("red.global.add.v4.f32 [%0], {%1,%2,%3,%4};"
                     :: "l"(yd + c), "f"(v.x), "f"(v.y), "f"(v.z), "f"(v.w)
                     : "memory");
    }
}

// ---------------- GEMM 96x96 + bias + relu: H = relu((Y*iI) @ W + b) --------
// 256 thr / block, 2 nodes per warp -> 16 nodes per block. fp32 throughout.
__global__ void k_gemm96(const float* __restrict__ W, const float* __restrict__ b) {
    __shared__ float Ws[96 * 96];
    __shared__ float bs[96];
    __shared__ float rows[8][2][96];
    int tid = threadIdx.x, wid = tid >> 5, lane = tid & 31;
    for (int i = tid; i < 96 * 96; i += 256) Ws[i] = W[i];
    if (tid < 96) bs[tid] = b[tid];
    int n0 = blockIdx.x * 16 + wid * 2;
    float s0 = g_iI[n0], s1 = g_iI[n0 + 1];
    const float* y0 = g_Y + n0 * 96;
    const float* y1 = y0 + 96;
    rows[wid][0][lane]      = y0[lane]      * s0;
    rows[wid][0][lane + 32] = y0[lane + 32] * s0;
    rows[wid][0][lane + 64] = y0[lane + 64] * s0;
    rows[wid][1][lane]      = y1[lane]      * s1;
    rows[wid][1][lane + 32] = y1[lane + 32] * s1;
    rows[wid][1][lane + 64] = y1[lane + 64] * s1;
    __syncthreads();
    float a00 = bs[lane], a01 = bs[lane + 32], a02 = bs[lane + 64];
    float a10 = a00, a11 = a01, a12 = a02;
#pragma unroll 8
    for (int k = 0; k < 96; k++) {
        float r0 = rows[wid][0][k], r1 = rows[wid][1][k];
        float w0 = Ws[k * 96 + lane];
        float w1 = Ws[k * 96 + lane + 32];
        float w2 = Ws[k * 96 + lane + 64];
        a00 += r0 * w0; a01 += r0 * w1; a02 += r0 * w2;
        a10 += r1 * w0; a11 += r1 * w1; a12 += r1 * w2;
    }
    float* o0 = g_H + n0 * 96;
    float* o1 = o0 + 96;
    o0[lane]      = fmaxf(a00, 0.f);
    o0[lane + 32] = fmaxf(a01, 0.f);
    o0[lane + 64] = fmaxf(a02, 0.f);
    o1[lane]      = fmaxf(a10, 0.f);
    o1[lane + 32] = fmaxf(a11, 0.f);
    o1[lane + 64] = fmaxf(a12, 0.f);
}

// ---------------- final 96x16 GEMM + log_softmax ---------------------------
// 2 nodes per warp: lanes 0-15 -> node n0, lanes 16-31 -> node n0+1.
__global__ void k_out(const float* __restrict__ W, const float* __restrict__ b,
                      float* __restrict__ out) {
    __shared__ float Ws[96 * 16];
    __shared__ float bs[16];
    __shared__ float rows[8][2][96];
    int tid = threadIdx.x, wid = tid >> 5, lane = tid & 31;
    for (int i = tid; i < 96 * 16; i += 256) Ws[i] = W[i];
    if (tid < 16) bs[tid] = b[tid];
    int h = lane >> 4, c = lane & 15;
    int n = blockIdx.x * 16 + wid * 2 + h;
    float s = g_iI[n];
    const float* yr = g_Y + n * 96;
    for (int k = c; k < 96; k += 16) rows[wid][h][k] = yr[k] * s;
    __syncthreads();
    float acc = bs[c];
#pragma unroll 8
    for (int k = 0; k < 96; k++) acc += rows[wid][h][k] * Ws[k * 16 + c];
    // log_softmax over the 16-lane group
    float m = acc;
#pragma unroll
    for (int o = 8; o; o >>= 1) m = fmaxf(m, __shfl_xor_sync(0xffffffffu, m, o, 16));
    float e = expf(acc - m);
    float ssum = e;
#pragma unroll
    for (int o = 8; o; o >>= 1) ssum += __shfl_xor_sync(0xffffffffu, ssum, o, 16);
    out[n * 16 + c] = acc - m - logf(ssum);
}

// ---------------- launch ----------------------------------------------------
extern "C" void kernel_launch(void* const* d_in, const int* in_sizes, int n_in,
                              void* d_out, int out_size) {
    const float* feat = (const float*)d_in[0];
    const float* ew   = (const float*)d_in[1];
    const int*   src  = (const int*)  d_in[2];
    const int*   dst  = (const int*)  d_in[3];
    const float* W0   = (const float*)d_in[4];
    const float* b0   = (const float*)d_in[5];
    const float* W1   = (const float*)d_in[6];
    const float* b1   = (const float*)d_in[7];
    const float* W2   = (const float*)d_in[8];
    const float* b2   = (const float*)d_in[9];
    float* out = (float*)d_out;

    // layer dropout keys: fold_in(key(42), l) = threefry((0,42), (0,l))
    uint32_t lk0[3], lk1[3];
    for (int l = 0; l < 3; l++) {
        uint32_t a = 0u, b = (uint32_t)l;
        tf2x32(0u, 42u, a, b);
        lk0[l] = a; lk1[l] = b;
    }

    float* gH = nullptr;
    cudaGetSymbolAddress((void**)&gH, g_H);

    const int TPB = 256;
    int nb_n = (NN + TPB - 1) / TPB;
    int nb_e = (NE + TPB - 1) / TPB;
    int nb_p = (ST / 4 + TPB - 1) / TPB;   // 1,200,000 threads
    int nb_e8 = (NE * 8) / TPB;            // 25000 exact
    int nb_g = NN / 16;                    // 3125 exact

    k_zero<<<nb_n, TPB>>>();
    k_count<<<nb_e, TPB>>>(src, dst);
    k_fin<<<nb_n, TPB>>>();

    // layer 0
    k_prep<<<nb_p, TPB>>>(feat, lk0[0], lk1[0]);
    k_edge<<<nb_e8, TPB>>>(ew, src, dst);
    k_gemm96<<<nb_g, TPB>>>(W0, b0);
    // layer 1
    k_prep<<<nb_p, TPB>>>(gH, lk0[1], lk1[1]);
    k_edge<<<nb_e8, TPB>>>(ew, src, dst);
    k_gemm96<<<nb_g, TPB>>>(W1, b1);
    // layer 2
    k_prep<<<nb_p, TPB>>>(gH, lk0[2], lk1[2]);
    k_edge<<<nb_e8, TPB>>>(ew, src, dst);
    k_out<<<nb_g, TPB>>>(W2, b2, out);
}

// round 7
// speedup vs baseline: 1.0751x; 1.0751x over previous
#include <cuda_runtime.h>
#include <stdint.h>

#define NN 50000
#define NE 800000
#define D  96
#define NC 16
#define ST (NN*D)        // 4,800,000

// ---------------- scratch (static device globals; no allocation) ----------
__device__ __align__(16) float g_X[ST];   // dropout+scaled input to message pass
__device__ __align__(16) float g_Y[ST];   // aggregation output (iI applied)
__device__ __align__(16) float g_H[ST];   // layer output
__device__ int   g_cO[NN];
__device__ int   g_cI[NN];
__device__ float g_iO[NN];
__device__ float g_iI[NN];
__device__ int   g_off[NN + 1];           // CSR offsets by dst
__device__ int   g_cur[NN];               // fill cursors
__device__ uint2 g_ep[NE];                // packed (src, weight-bits) sorted by dst

// ---------------- threefry2x32-20 (matches JAX) ----------------------------
__device__ __host__ __forceinline__ void tf2x32(uint32_t k0, uint32_t k1,
                                                uint32_t& x0, uint32_t& x1) {
    uint32_t k2 = k0 ^ k1 ^ 0x1BD11BDAu;
    x0 += k0; x1 += k1;
#define TF_R(r) { x0 += x1; x1 = (x1 << (r)) | (x1 >> (32 - (r))); x1 ^= x0; }
    TF_R(13) TF_R(15) TF_R(26) TF_R(6)   x0 += k1; x1 += k2 + 1u;
    TF_R(17) TF_R(29) TF_R(16) TF_R(24)  x0 += k2; x1 += k0 + 2u;
    TF_R(13) TF_R(15) TF_R(26) TF_R(6)   x0 += k0; x1 += k1 + 3u;
    TF_R(17) TF_R(29) TF_R(16) TF_R(24)  x0 += k1; x1 += k2 + 4u;
    TF_R(13) TF_R(15) TF_R(26) TF_R(6)   x0 += k2; x1 += k0 + 5u;
#undef TF_R
}

// ---------------- degree kernels -------------------------------------------
__global__ void k_zero() {
    int i = blockIdx.x * blockDim.x + threadIdx.x;
    if (i < NN) { g_cO[i] = 0; g_cI[i] = 0; }
}

__global__ void k_count(const int* __restrict__ src, const int* __restrict__ dst) {
    int e = blockIdx.x * blockDim.x + threadIdx.x;
    if (e < NE) {
        atomicAdd(&g_cO[src[e]], 1);
        atomicAdd(&g_cI[dst[e]], 1);
    }
}

__global__ void k_fin() {
    int i = blockIdx.x * blockDim.x + threadIdx.x;
    if (i < NN) {
        g_iO[i] = (float)(1.0 / sqrt((double)max(g_cO[i], 1)));
        g_iI[i] = (float)(1.0 / sqrt((double)max(g_cI[i], 1)));
    }
}

// ---------------- CSR build: scan + fill ------------------------------------
__global__ void k_scan() {    // single block, 1024 threads
    __shared__ int part[1024];
    const int CH = (NN + 1023) / 1024;     // 49
    int t = threadIdx.x;
    int beg = t * CH, end = min(beg + CH, NN);
    int s = 0;
    for (int i = beg; i < end; i++) s += g_cI[i];
    part[t] = s;
    __syncthreads();
    for (int off = 1; off < 1024; off <<= 1) {
        int v = (t >= off) ? part[t - off] : 0;
        __syncthreads();
        part[t] += v;
        __syncthreads();
    }
    int run = (t > 0) ? part[t - 1] : 0;
    for (int i = beg; i < end; i++) {
        g_off[i] = run;
        g_cur[i] = run;
        run += g_cI[i];
    }
    if (t == 1023) g_off[NN] = run;        // == NE
}

__global__ void k_fill(const int* __restrict__ src, const int* __restrict__ dst,
                       const float* __restrict__ ew) {
    int e = blockIdx.x * blockDim.x + threadIdx.x;
    if (e < NE) {
        int d = dst[e];
        int slot = atomicAdd(&g_cur[d], 1);
        g_ep[slot] = make_uint2((uint32_t)src[e], __float_as_uint(ew[e]));
    }
}

// ---------------- dropout + D_out^-1/2 scale --------------------------------
// JAX partitionable threefry: bits[i] = out0 ^ out1 of threefry(key, (0, i)).
// keep ⇔ msb(bits) == 0.
__global__ void k_prep(const float* __restrict__ hin, uint32_t k0, uint32_t k1) {
    int t = blockIdx.x * blockDim.x + threadIdx.x;
    if (t >= ST / 4) return;
    int j = t * 4;
    float4 a = *(const float4*)(hin + j);
    float s = g_iO[j / D] * 2.0f;             // *2 = /(1-p)
    float v[4] = {a.x, a.y, a.z, a.w};
#pragma unroll
    for (int i = 0; i < 4; i++) {
        uint32_t x0 = 0u, x1 = (uint32_t)(j + i);
        tf2x32(k0, k1, x0, x1);
        uint32_t bits = x0 ^ x1;
        v[i] = (bits < 0x80000000u) ? v[i] * s : 0.0f;
    }
    *(float4*)(g_X + j) = make_float4(v[0], v[1], v[2], v[3]);
}

// ---------------- aggregation: warp per dst node (CSR gather) ---------------
// Y[n] = iI[n] * sum_{e: dst=n} w_e * X[src_e].  Each lane owns 3 columns.
__global__ void k_agg() {
    int warp = (blockIdx.x * blockDim.x + threadIdx.x) >> 5;
    if (warp >= NN) return;
    int lane = threadIdx.x & 31;
    int beg = g_off[warp], end = g_off[warp + 1];
    float a0 = 0.f, a1 = 0.f, a2 = 0.f;
    int i = beg;
    for (; i + 2 <= end; i += 2) {
        uint2 p0 = g_ep[i], p1 = g_ep[i + 1];
        const float* x0 = g_X + (int)p0.x * D;
        const float* x1 = g_X + (int)p1.x * D;
        float w0 = __uint_as_float(p0.y);
        float w1 = __uint_as_float(p1.y);
        float r00 = x0[lane], r01 = x0[lane + 32], r02 = x0[lane + 64];
        float r10 = x1[lane], r11 = x1[lane + 32], r12 = x1[lane + 64];
        a0 += w0 * r00; a1 += w0 * r01; a2 += w0 * r02;
        a0 += w1 * r10; a1 += w1 * r11; a2 += w1 * r12;
    }
    if (i < end) {
        uint2 p = g_ep[i];
        const float* x = g_X + (int)p.x * D;
        float w = __uint_as_float(p.y);
        a0 += w * x[lane]; a1 += w * x[lane + 32]; a2 += w * x[lane + 64];
    }
    float sc = g_iI[warp];
    float* y = g_Y + warp * D;
    y[lane]      = a0 * sc;
    y[lane + 32] = a1 * sc;
    y[lane + 64] = a2 * sc;
}

// ---------------- GEMM 96x96 + bias + relu: H = relu(Y @ W + b) -------------
// 8 warps/block, 8 nodes/warp (64 nodes/block). Rows in smem, W via L1 (__ldg).
__global__ void k_gemm96(const float* __restrict__ W, const float* __restrict__ b) {
    __shared__ float rows[8][8][96];   // 24.5 KB
    int tid = threadIdx.x, wid = tid >> 5, lane = tid & 31;
    int base = blockIdx.x * 64 + wid * 8;
#pragma unroll
    for (int j = 0; j < 8; j++) {
        int n = base + j;
        if (n < NN) {
            const float* yr = g_Y + n * 96;
            rows[wid][j][lane]      = yr[lane];
            rows[wid][j][lane + 32] = yr[lane + 32];
            rows[wid][j][lane + 64] = yr[lane + 64];
        }
    }
    float b0 = __ldg(b + lane), b1 = __ldg(b + lane + 32), b2 = __ldg(b + lane + 64);
    float acc[8][3];
#pragma unroll
    for (int j = 0; j < 8; j++) { acc[j][0] = b0; acc[j][1] = b1; acc[j][2] = b2; }
    __syncwarp();
#pragma unroll 4
    for (int k = 0; k < 96; k++) {
        float w0 = __ldg(W + k * 96 + lane);
        float w1 = __ldg(W + k * 96 + lane + 32);
        float w2 = __ldg(W + k * 96 + lane + 64);
#pragma unroll
        for (int j = 0; j < 8; j++) {
            float r = rows[wid][j][k];
            acc[j][0] += r * w0; acc[j][1] += r * w1; acc[j][2] += r * w2;
        }
    }
#pragma unroll
    for (int j = 0; j < 8; j++) {
        int n = base + j;
        if (n < NN) {
            float* o = g_H + n * 96;
            o[lane]      = fmaxf(acc[j][0], 0.f);
            o[lane + 32] = fmaxf(acc[j][1], 0.f);
            o[lane + 64] = fmaxf(acc[j][2], 0.f);
        }
    }
}

// ---------------- final 96x16 GEMM + log_softmax ---------------------------
// 2 nodes per warp: lanes 0-15 -> node n0, lanes 16-31 -> node n0+1.
__global__ void k_out(const float* __restrict__ W, const float* __restrict__ b,
                      float* __restrict__ out) {
    __shared__ float Ws[96 * 16];
    __shared__ float bs[16];
    __shared__ float rows[8][2][96];
    int tid = threadIdx.x, wid = tid >> 5, lane = tid & 31;
    for (int i = tid; i < 96 * 16; i += 256) Ws[i] = W[i];
    if (tid < 16) bs[tid] = b[tid];
    int h = lane >> 4, c = lane & 15;
    int n = blockIdx.x * 16 + wid * 2 + h;
    const float* yr = g_Y + n * 96;
    for (int k = c; k < 96; k += 16) rows[wid][h][k] = yr[k];
    __syncthreads();
    float acc = bs[c];
#pragma unroll 8
    for (int k = 0; k < 96; k++) acc += rows[wid][h][k] * Ws[k * 16 + c];
    // log_softmax over the 16-lane group
    float m = acc;
#pragma unroll
    for (int o = 8; o; o >>= 1) m = fmaxf(m, __shfl_xor_sync(0xffffffffu, m, o, 16));
    float e = expf(acc - m);
    float ssum = e;
#pragma unroll
    for (int o = 8; o; o >>= 1) ssum += __shfl_xor_sync(0xffffffffu, ssum, o, 16);
    out[n * 16 + c] = acc - m - logf(ssum);
}

// ---------------- launch ----------------------------------------------------
extern "C" void kernel_launch(void* const* d_in, const int* in_sizes, int n_in,
                              void* d_out, int out_size) {
    const float* feat = (const float*)d_in[0];
    const float* ew   = (const float*)d_in[1];
    const int*   src  = (const int*)  d_in[2];
    const int*   dst  = (const int*)  d_in[3];
    const float* W0   = (const float*)d_in[4];
    const float* b0   = (const float*)d_in[5];
    const float* W1   = (const float*)d_in[6];
    const float* b1   = (const float*)d_in[7];
    const float* W2   = (const float*)d_in[8];
    const float* b2   = (const float*)d_in[9];
    float* out = (float*)d_out;

    // layer dropout keys: fold_in(key(42), l) = threefry((0,42), (0,l))
    uint32_t lk0[3], lk1[3];
    for (int l = 0; l < 3; l++) {
        uint32_t a = 0u, b = (uint32_t)l;
        tf2x32(0u, 42u, a, b);
        lk0[l] = a; lk1[l] = b;
    }

    float* gH = nullptr;
    cudaGetSymbolAddress((void**)&gH, g_H);

    const int TPB = 256;
    int nb_n = (NN + TPB - 1) / TPB;
    int nb_e = (NE + TPB - 1) / TPB;
    int nb_p = (ST / 4 + TPB - 1) / TPB;   // 1,200,000 / 256
    int nb_a = (NN * 32 + TPB - 1) / TPB;  // warp per node -> 6250
    int nb_g = (NN + 63) / 64;             // 782
    int nb_o = NN / 16;                    // 3125 exact

    // graph preprocessing (reused by all 3 layers)
    k_zero<<<nb_n, TPB>>>();
    k_count<<<nb_e, TPB>>>(src, dst);
    k_fin<<<nb_n, TPB>>>();
    k_scan<<<1, 1024>>>();
    k_fill<<<nb_e, TPB>>>(src, dst, ew);

    // layer 0
    k_prep<<<nb_p, TPB>>>(feat, lk0[0], lk1[0]);
    k_agg<<<nb_a, TPB>>>();
    k_gemm96<<<nb_g, TPB>>>(W0, b0);
    // layer 1
    k_prep<<<nb_p, TPB>>>(gH, lk0[1], lk1[1]);
    k_agg<<<nb_a, TPB>>>();
    k_gemm96<<<nb_g, TPB>>>(W1, b1);
    // layer 2
    k_prep<<<nb_p, TPB>>>(gH, lk0[2], lk1[2]);
    k_agg<<<nb_a, TPB>>>();
    k_out<<<nb_o, TPB>>>(W2, b2, out);
}

// round 8
// speedup vs baseline: 1.3734x; 1.2775x over previous
#include <cuda_runtime.h>
#include <stdint.h>

#define NN 50000
#define NE 800000
#define D  96
#define NC 16
#define ST (NN*D)        // 4,800,000
#define SCB 49           // scan blocks: 49 * 1024 >= NN

// ---------------- scratch (static device globals; no allocation) ----------
__device__ __align__(16) float g_X[ST];   // dropout+scaled input to message pass
__device__ __align__(16) float g_Y[ST];   // aggregation output (iI applied)
__device__ __align__(16) float g_H[ST];   // layer output
__device__ int   g_cO[NN];
__device__ int   g_cI[NN];
__device__ float g_iO[NN];
__device__ float g_iI[NN];
__device__ int   g_off[NN + 1];           // CSR offsets by dst
__device__ int   g_cur[NN];               // fill cursors
__device__ int   g_part[SCB];             // per-block totals
__device__ int   g_partx[SCB];            // exclusive scan of totals
__device__ uint2 g_ep[NE];                // packed (src, weight-bits) sorted by dst

// ---------------- threefry2x32-20 (matches JAX) ----------------------------
__device__ __host__ __forceinline__ void tf2x32(uint32_t k0, uint32_t k1,
                                                uint32_t& x0, uint32_t& x1) {
    uint32_t k2 = k0 ^ k1 ^ 0x1BD11BDAu;
    x0 += k0; x1 += k1;
#define TF_R(r) { x0 += x1; x1 = (x1 << (r)) | (x1 >> (32 - (r))); x1 ^= x0; }
    TF_R(13) TF_R(15) TF_R(26) TF_R(6)   x0 += k1; x1 += k2 + 1u;
    TF_R(17) TF_R(29) TF_R(16) TF_R(24)  x0 += k2; x1 += k0 + 2u;
    TF_R(13) TF_R(15) TF_R(26) TF_R(6)   x0 += k0; x1 += k1 + 3u;
    TF_R(17) TF_R(29) TF_R(16) TF_R(24)  x0 += k1; x1 += k2 + 4u;
    TF_R(13) TF_R(15) TF_R(26) TF_R(6)   x0 += k2; x1 += k0 + 5u;
#undef TF_R
}

// ---------------- degree kernels -------------------------------------------
__global__ void k_zero() {
    int i = blockIdx.x * blockDim.x + threadIdx.x;
    if (i < NN) { g_cO[i] = 0; g_cI[i] = 0; }
}

__global__ void k_count(const int* __restrict__ src, const int* __restrict__ dst) {
    int e = blockIdx.x * blockDim.x + threadIdx.x;
    if (e < NE) {
        atomicAdd(&g_cO[src[e]], 1);
        atomicAdd(&g_cI[dst[e]], 1);
    }
}

__global__ void k_fin() {
    int i = blockIdx.x * blockDim.x + threadIdx.x;
    if (i < NN) {
        g_iO[i] = (float)(1.0 / sqrt((double)max(g_cO[i], 1)));
        g_iI[i] = (float)(1.0 / sqrt((double)max(g_cI[i], 1)));
    }
}

// ---------------- CSR build: 3-phase multi-block scan -----------------------
// Phase A: per-block (1024 elems) local exclusive offsets + block total.
__global__ void k_scanA() {
    __shared__ int sh[256];
    int t = threadIdx.x;
    int base = blockIdx.x * 1024 + t * 4;
    int v[4], s = 0;
#pragma unroll
    for (int j = 0; j < 4; j++) {
        v[j] = (base + j < NN) ? g_cI[base + j] : 0;
        s += v[j];
    }
    sh[t] = s;
    __syncthreads();
#pragma unroll
    for (int off = 1; off < 256; off <<= 1) {
        int x = (t >= off) ? sh[t - off] : 0;
        __syncthreads();
        sh[t] += x;
        __syncthreads();
    }
    int run = sh[t] - s;   // exclusive prefix within block
#pragma unroll
    for (int j = 0; j < 4; j++) {
        if (base + j < NN) g_off[base + j] = run;
        run += v[j];
    }
    if (t == 255) g_part[blockIdx.x] = sh[255];
}

// Phase B: exclusive scan of 49 block totals (trivial).
__global__ void k_scanB() {
    int run = 0;
#pragma unroll
    for (int i = 0; i < SCB; i++) { g_partx[i] = run; run += g_part[i]; }
}

// Phase C: add block base, init cursors, terminate offsets.
__global__ void k_scanC() {
    int t = threadIdx.x;
    int base = blockIdx.x * 1024 + t * 4;
    int add = g_partx[blockIdx.x];
#pragma unroll
    for (int j = 0; j < 4; j++) {
        int i = base + j;
        if (i < NN) {
            int o = g_off[i] + add;
            g_off[i] = o;
            g_cur[i] = o;
        }
    }
    if (blockIdx.x == 0 && t == 0) g_off[NN] = NE;
}

__global__ void k_fill(const int* __restrict__ src, const int* __restrict__ dst,
                       const float* __restrict__ ew) {
    int e = blockIdx.x * blockDim.x + threadIdx.x;
    if (e < NE) {
        int d = dst[e];
        int slot = atomicAdd(&g_cur[d], 1);
        g_ep[slot] = make_uint2((uint32_t)src[e], __float_as_uint(ew[e]));
    }
}

// ---------------- dropout + D_out^-1/2 scale --------------------------------
// JAX partitionable threefry: bits[i] = out0 ^ out1 of threefry(key, (0, i)).
// keep ⇔ msb(bits) == 0.
__global__ void k_prep(const float* __restrict__ hin, uint32_t k0, uint32_t k1) {
    int t = blockIdx.x * blockDim.x + threadIdx.x;
    if (t >= ST / 4) return;
    int j = t * 4;
    float4 a = *(const float4*)(hin + j);
    float s = g_iO[j / D] * 2.0f;             // *2 = /(1-p)
    float v[4] = {a.x, a.y, a.z, a.w};
#pragma unroll
    for (int i = 0; i < 4; i++) {
        uint32_t x0 = 0u, x1 = (uint32_t)(j + i);
        tf2x32(k0, k1, x0, x1);
        uint32_t bits = x0 ^ x1;
        v[i] = (bits < 0x80000000u) ? v[i] * s : 0.0f;
    }
    *(float4*)(g_X + j) = make_float4(v[0], v[1], v[2], v[3]);
}

// ---------------- aggregation: warp per dst node (CSR gather) ---------------
// Y[n] = iI[n] * sum_{e: dst=n} w_e * X[src_e].  Each lane owns 3 columns.
__global__ void k_agg() {
    int warp = (blockIdx.x * blockDim.x + threadIdx.x) >> 5;
    if (warp >= NN) return;
    int lane = threadIdx.x & 31;
    int beg = g_off[warp], end = g_off[warp + 1];
    float a0 = 0.f, a1 = 0.f, a2 = 0.f;
    int i = beg;
    for (; i + 2 <= end; i += 2) {
        uint2 p0 = g_ep[i], p1 = g_ep[i + 1];
        const float* x0 = g_X + (int)p0.x * D;
        const float* x1 = g_X + (int)p1.x * D;
        float w0 = __uint_as_float(p0.y);
        float w1 = __uint_as_float(p1.y);
        float r00 = x0[lane], r01 = x0[lane + 32], r02 = x0[lane + 64];
        float r10 = x1[lane], r11 = x1[lane + 32], r12 = x1[lane + 64];
        a0 += w0 * r00; a1 += w0 * r01; a2 += w0 * r02;
        a0 += w1 * r10; a1 += w1 * r11; a2 += w1 * r12;
    }
    if (i < end) {
        uint2 p = g_ep[i];
        const float* x = g_X + (int)p.x * D;
        float w = __uint_as_float(p.y);
        a0 += w * x[lane]; a1 += w * x[lane + 32]; a2 += w * x[lane + 64];
    }
    float sc = g_iI[warp];
    float* y = g_Y + warp * D;
    y[lane]      = a0 * sc;
    y[lane + 32] = a1 * sc;
    y[lane + 64] = a2 * sc;
}

// ---------------- GEMM 96x96 + bias + relu: H = relu(Y @ W + b) -------------
// 8 warps/block, 8 nodes/warp (64 nodes/block). Rows in smem, W via L1 (__ldg).
__global__ void k_gemm96(const float* __restrict__ W, const float* __restrict__ b) {
    __shared__ float rows[8][8][96];   // 24.5 KB
    int tid = threadIdx.x, wid = tid >> 5, lane = tid & 31;
    int base = blockIdx.x * 64 + wid * 8;
#pragma unroll
    for (int j = 0; j < 8; j++) {
        int n = base + j;
        if (n < NN) {
            const float* yr = g_Y + n * 96;
            rows[wid][j][lane]      = yr[lane];
            rows[wid][j][lane + 32] = yr[lane + 32];
            rows[wid][j][lane + 64] = yr[lane + 64];
        }
    }
    float b0 = __ldg(b + lane), b1 = __ldg(b + lane + 32), b2 = __ldg(b + lane + 64);
    float acc[8][3];
#pragma unroll
    for (int j = 0; j < 8; j++) { acc[j][0] = b0; acc[j][1] = b1; acc[j][2] = b2; }
    __syncwarp();
#pragma unroll 4
    for (int k = 0; k < 96; k++) {
        float w0 = __ldg(W + k * 96 + lane);
        float w1 = __ldg(W + k * 96 + lane + 32);
        float w2 = __ldg(W + k * 96 + lane + 64);
#pragma unroll
        for (int j = 0; j < 8; j++) {
            float r = rows[wid][j][k];
            acc[j][0] += r * w0; acc[j][1] += r * w1; acc[j][2] += r * w2;
        }
    }
#pragma unroll
    for (int j = 0; j < 8; j++) {
        int n = base + j;
        if (n < NN) {
            float* o = g_H + n * 96;
            o[lane]      = fmaxf(acc[j][0], 0.f);
            o[lane + 32] = fmaxf(acc[j][1], 0.f);
            o[lane + 64] = fmaxf(acc[j][2], 0.f);
        }
    }
}

// ---------------- final 96x16 GEMM + log_softmax ---------------------------
// 2 nodes per warp: lanes 0-15 -> node n0, lanes 16-31 -> node n0+1.
__global__ void k_out(const float* __restrict__ W, const float* __restrict__ b,
                      float* __restrict__ out) {
    __shared__ float Ws[96 * 16];
    __shared__ float bs[16];
    __shared__ float rows[8][2][96];
    int tid = threadIdx.x, wid = tid >> 5, lane = tid & 31;
    for (int i = tid; i < 96 * 16; i += 256) Ws[i] = W[i];
    if (tid < 16) bs[tid] = b[tid];
    int h = lane >> 4, c = lane & 15;
    int n = blockIdx.x * 16 + wid * 2 + h;
    const float* yr = g_Y + n * 96;
    for (int k = c; k < 96; k += 16) rows[wid][h][k] = yr[k];
    __syncthreads();
    float acc = bs[c];
#pragma unroll 8
    for (int k = 0; k < 96; k++) acc += rows[wid][h][k] * Ws[k * 16 + c];
    // log_softmax over the 16-lane group
    float m = acc;
#pragma unroll
    for (int o = 8; o; o >>= 1) m = fmaxf(m, __shfl_xor_sync(0xffffffffu, m, o, 16));
    float e = expf(acc - m);
    float ssum = e;
#pragma unroll
    for (int o = 8; o; o >>= 1) ssum += __shfl_xor_sync(0xffffffffu, ssum, o, 16);
    out[n * 16 + c] = acc - m - logf(ssum);
}

// ---------------- launch ----------------------------------------------------
extern "C" void kernel_launch(void* const* d_in, const int* in_sizes, int n_in,
                              void* d_out, int out_size) {
    const float* feat = (const float*)d_in[0];
    const float* ew   = (const float*)d_in[1];
    const int*   src  = (const int*)  d_in[2];
    const int*   dst  = (const int*)  d_in[3];
    const float* W0   = (const float*)d_in[4];
    const float* b0   = (const float*)d_in[5];
    const float* W1   = (const float*)d_in[6];
    const float* b1   = (const float*)d_in[7];
    const float* W2   = (const float*)d_in[8];
    const float* b2   = (const float*)d_in[9];
    float* out = (float*)d_out;

    // layer dropout keys: fold_in(key(42), l) = threefry((0,42), (0,l))
    uint32_t lk0[3], lk1[3];
    for (int l = 0; l < 3; l++) {
        uint32_t a = 0u, b = (uint32_t)l;
        tf2x32(0u, 42u, a, b);
        lk0[l] = a; lk1[l] = b;
    }

    float* gH = nullptr;
    cudaGetSymbolAddress((void**)&gH, g_H);

    const int TPB = 256;
    int nb_n = (NN + TPB - 1) / TPB;
    int nb_e = (NE + TPB - 1) / TPB;
    int nb_p = (ST / 4 + TPB - 1) / TPB;   // 1,200,000 / 256
    int nb_a = (NN * 32 + TPB - 1) / TPB;  // warp per node -> 6250
    int nb_g = (NN + 63) / 64;             // 782
    int nb_o = NN / 16;                    // 3125 exact

    // graph preprocessing (reused by all 3 layers)
    k_zero<<<nb_n, TPB>>>();
    k_count<<<nb_e, TPB>>>(src, dst);
    k_fin<<<nb_n, TPB>>>();
    k_scanA<<<SCB, 256>>>();
    k_scanB<<<1, 1>>>();
    k_scanC<<<SCB, 256>>>();
    k_fill<<<nb_e, TPB>>>(src, dst, ew);

    // layer 0
    k_prep<<<nb_p, TPB>>>(feat, lk0[0], lk1[0]);
    k_agg<<<nb_a, TPB>>>();
    k_gemm96<<<nb_g, TPB>>>(W0, b0);
    // layer 1
    k_prep<<<nb_p, TPB>>>(gH, lk0[1], lk1[1]);
    k_agg<<<nb_a, TPB>>>();
    k_gemm96<<<nb_g, TPB>>>(W1, b1);
    // layer 2
    k_prep<<<nb_p, TPB>>>(gH, lk0[2], lk1[2]);
    k_agg<<<nb_a, TPB>>>();
    k_out<<<nb_o, TPB>>>(W2, b2, out);
}